// round 5
// baseline (speedup 1.0000x reference)
#include <cuda_runtime.h>
#include <math.h>

// Problem constants (fixed shapes from setup_inputs)
#define LL 4
#define BB 8
#define NS 1200
#define NL 128
#define CC 768
#define HH 448
#define WW 448
#define GS 56            // H/8   (grid cols, small)
#define GL 16            // H/28  (grid cols, large)
#define LB (LL*BB)       // 32
#define CWS ((NS+31)/32) // 38 colv words per l (small)
#define CWL ((NL+31)/32) // 4  colv words per l (large)
#define NBS 150          // blocks per lb for small scale in k_dist (1200/8)
#define NBL 16           // blocks per lb for large scale in k_dist (128/8)
#define STATS_BX 5       // ceil(NS/256)
#define STATS_BLOCKS (STATS_BX * 2 * LB)   // 320

// Scratch (no allocations -> __device__ globals). Device-code refs only.
__device__ float g_dist_s[LB*NS];
__device__ float g_dist_l[LB*NL];
__device__ unsigned g_colv_s[LL*CWS];
__device__ unsigned g_colv_l[LL*CWL];
__device__ float g_sp[2*LB];
__device__ float g_sn[2*LB];
__device__ int   g_cp[2*LB];
__device__ int   g_cn[2*LB];
__device__ unsigned g_done;

// ---------------------------------------------------------------------------
// 1) Tiny zeroing kernel (colv bitmasks, accumulators, done counter).
// ---------------------------------------------------------------------------
__global__ void k_zero() {
    int t = threadIdx.x;   // 256 threads, 1 block
    if (t < LL*CWS) g_colv_s[t] = 0u;
    if (t < LL*CWL) g_colv_l[t] = 0u;
    if (t < 2*LB) { g_sp[t] = 0.f; g_sn[t] = 0.f; g_cp[t] = 0; g_cn[t] = 0; }
    if (t == 0) g_done = 0u;
}

// ---------------------------------------------------------------------------
// 2) Main HBM-bound pass (both scales in one launch):
//    per row (l,b,n): dist = sqrt(sum_c (anchor-sel)^2) and
//    abssum = sum_c |sel| -> sets colv bit if nonzero.
//    One warp per row, float4 loads, anchor staged in SMEM.
// ---------------------------------------------------------------------------
__global__ void k_dist(const float* __restrict__ sel_s,
                       const float* __restrict__ ker_s,
                       const float* __restrict__ sel_l,
                       const float* __restrict__ ker_l) {
    __shared__ float sa[CC];
    int lb = blockIdx.y;   // l*B + b
    int l  = lb / BB;
    int scale = (blockIdx.x >= NBS) ? 1 : 0;
    int bx = scale ? (blockIdx.x - NBS) : blockIdx.x;
    int N = scale ? NL : NS;
    const float* sel = scale ? sel_l : sel_s;
    const float* ker = scale ? ker_l : ker_s;

    const float* a = ker + (size_t)lb * CC;   // kernel (L,B,C,1) -> contiguous C
    for (int i = threadIdx.x; i < CC; i += blockDim.x) sa[i] = a[i];
    __syncthreads();

    int warp = threadIdx.x >> 5;
    int lane = threadIdx.x & 31;
    int n = bx * 8 + warp;
    if (n >= N) return;

    const float4* row = (const float4*)(sel + ((size_t)lb * N + n) * CC);
    const float4* av  = (const float4*)sa;

    float s2 = 0.f, sab = 0.f;
#pragma unroll
    for (int k = 0; k < CC/128; k++) {   // 6 iterations, 192 float4 per row
        float4 v  = row[k*32 + lane];
        float4 aa = av [k*32 + lane];
        float d0 = aa.x - v.x, d1 = aa.y - v.y;
        float d2 = aa.z - v.z, d3 = aa.w - v.w;
        s2  = fmaf(d0, d0, s2); s2 = fmaf(d1, d1, s2);
        s2  = fmaf(d2, d2, s2); s2 = fmaf(d3, d3, s2);
        sab += fabsf(v.x) + fabsf(v.y) + fabsf(v.z) + fabsf(v.w);
    }
#pragma unroll
    for (int o = 16; o; o >>= 1) {
        s2  += __shfl_xor_sync(0xFFFFFFFFu, s2,  o);
        sab += __shfl_xor_sync(0xFFFFFFFFu, sab, o);
    }
    if (lane == 0) {
        size_t off = (size_t)lb * N + n;
        if (scale == 0) {
            g_dist_s[off] = sqrtf(s2);
            if (sab != 0.f) atomicOr(&g_colv_s[l*CWS + (n >> 5)], 1u << (n & 31));
        } else {
            g_dist_l[off] = sqrtf(s2);
            if (sab != 0.f) atomicOr(&g_colv_l[l*CWL + (n >> 5)], 1u << (n & 31));
        }
    }
}

// ---------------------------------------------------------------------------
// 3) Masked accumulation + fused finalization (last block).
//    grid = (STATS_BX, 64): blockIdx.y = gb (scale*LB + lb).
//    Membership read directly from f_k sample (no precomputed mask).
// ---------------------------------------------------------------------------
__global__ void k_stats(const int* __restrict__ idx_s,
                        const int* __restrict__ idx_l,
                        const float* __restrict__ fk,
                        float* __restrict__ out) {
    int gb = blockIdx.y;
    int scale = gb / LB;      // 0 = s, 1 = l
    int lb = gb % LB;
    int l = lb / BB, b = lb % BB;
    int N = scale ? NL : NS;
    const float* dist = scale ? g_dist_l : g_dist_s;
    const unsigned* colv = scale ? (g_colv_l + l*CWL) : (g_colv_s + l*CWS);
    const int* idx = scale ? idx_l : idx_s;

    int n = blockIdx.x * blockDim.x + threadIdx.x;
    float sp = 0.f, sn = 0.f;
    int   cp = 0,   cn = 0;
    if (n < N && ((colv[n >> 5] >> (n & 31)) & 1u)) {
        int id = idx[((size_t)l*BB + b)*N + n];
        float d = dist[(size_t)lb*N + n];
        // membership: f_k sampled at the strided grid position of id
        int G = scale ? GL : GS;
        int S = scale ? 28 : 8;
        int gi = id / G, gj = id % G;
        bool mem = fk[(size_t)b*HH*WW + (size_t)gi*S*WW + gj*S] > 0.f;
        if (mem) { sp = d; cp = 1; } else { sn = d; cn = 1; }
    }

#pragma unroll
    for (int o = 16; o; o >>= 1) {
        sp += __shfl_xor_sync(0xFFFFFFFFu, sp, o);
        sn += __shfl_xor_sync(0xFFFFFFFFu, sn, o);
        cp += __shfl_xor_sync(0xFFFFFFFFu, cp, o);
        cn += __shfl_xor_sync(0xFFFFFFFFu, cn, o);
    }
    if ((threadIdx.x & 31) == 0) {
        if (sp != 0.f) atomicAdd(&g_sp[gb], sp);
        if (sn != 0.f) atomicAdd(&g_sn[gb], sn);
        if (cp)        atomicAdd(&g_cp[gb], cp);
        if (cn)        atomicAdd(&g_cn[gb], cn);
    }

    // ---- last-block finalization ----
    __shared__ bool is_last;
    __syncthreads();              // all block atomics issued
    if (threadIdx.x == 0) {
        __threadfence();
        unsigned prev = atomicAdd(&g_done, 1u);
        is_last = (prev == STATS_BLOCKS - 1);
    }
    __syncthreads();
    if (!is_last) return;

    __shared__ float s_loss[2*LB];
    __shared__ int   s_act [2*LB];
    int t = threadIdx.x;
    if (t < 2*LB) {
        int tcp = g_cp[t], tcn = g_cn[t];
        float ap = g_sp[t] / (float)(tcp > 1 ? tcp : 1);
        float an = g_sn[t] / (float)(tcn > 1 ? tcn : 1);
        float x = ap - an;
        float loss = (x > 0.f) ? (x + log1pf(expf(-x))) : log1pf(expf(x));
        s_loss[t] = loss;
        s_act[t]  = (tcp > 0 && tcn > 0) ? 1 : 0;
    }
    __syncthreads();
    if (t < 64) {
        float v = 0.f; int c = 0;
        if (t < LB) {                       // small scale: act_s
            if (s_act[t]) { v = s_loss[t]; c = 1; }
        } else {                            // large scale: act_l & act_s
            if (s_act[t] && s_act[t - LB]) { v = s_loss[t]; c = 1; }
        }
#pragma unroll
        for (int o = 16; o; o >>= 1) {
            v += __shfl_xor_sync(0xFFFFFFFFu, v, o);
            c += __shfl_xor_sync(0xFFFFFFFFu, c, o);
        }
        __shared__ float sv[2]; __shared__ int sc[2];
        int warp = t >> 5;
        if ((t & 31) == 0) { sv[warp] = v; sc[warp] = c; }
        __syncthreads();
        if (t == 0) {
            float total = sv[0] + sv[1];
            int times = sc[0] + sc[1];
            out[0] = (times > 0) ? total / (float)times : 0.f;
        }
    }
}

// ---------------------------------------------------------------------------
extern "C" void kernel_launch(void* const* d_in, const int* in_sizes, int n_in,
                              void* d_out, int out_size) {
    const float* sel_s = (const float*)d_in[0];
    const int*   idx_s = (const int*)  d_in[1];
    const float* sel_l = (const float*)d_in[2];
    const int*   idx_l = (const int*)  d_in[3];
    const float* ker_s = (const float*)d_in[4];
    const float* ker_l = (const float*)d_in[5];
    const float* fk    = (const float*)d_in[6];

    k_zero<<<1, 256>>>();

    dim3 gd(NBS + NBL, LB);
    k_dist<<<gd, 256>>>(sel_s, ker_s, sel_l, ker_l);

    dim3 gst(STATS_BX, 2*LB);   // (5, 64) = 320 blocks
    k_stats<<<gst, 256>>>(idx_s, idx_l, fk, (float*)d_out);
}

// round 6
// speedup vs baseline: 1.0840x; 1.0840x over previous
#include <cuda_runtime.h>
#include <math.h>

// Problem constants (fixed shapes from setup_inputs)
#define LL 4
#define BB 8
#define NS 1200
#define NL 128
#define CC 768
#define HH 448
#define WW 448
#define GS 56            // H/8   (grid cols, small)
#define GL 16            // H/28  (grid cols, large)
#define VS (GS*GS)       // 3136
#define VL (GL*GL)       // 256
#define LB (LL*BB)       // 32
#define NBS 150          // blocks per lb, small scale (1200/8)
#define NBL 16           // blocks per lb, large scale (128/8)
#define GDX (NBS+NBL)    // 166
#define NSAMP (BB*VS + BB*VL)   // 27136 mask samples
#define STATS_BX 5       // ceil(NS/256)
#define STATS_BLOCKS (STATS_BX * 2 * LB)   // 320

// Scratch (no allocations -> __device__ globals). Device-code refs only.
__device__ float g_dist_s[LB*NS];
__device__ float g_dist_l[LB*NL];
__device__ unsigned char g_nz_s[LL*NS*8];   // [l][n][b] nonzero flags
__device__ unsigned char g_nz_l[LL*NL*8];
__device__ unsigned char g_valid_s[BB*VS];
__device__ unsigned char g_valid_l[BB*VL];
__device__ float g_sp[2*LB];
__device__ float g_sn[2*LB];
__device__ int   g_cp[2*LB];
__device__ int   g_cn[2*LB];
__device__ unsigned g_done;

// ---------------------------------------------------------------------------
// 1) Main HBM-bound pass (both scales, one launch).
//    Per row (l,b,n): dist = sqrt(sum_c (anchor-sel)^2); nz byte = (sum|sel|!=0).
//    One warp per row, float4 loads, anchor staged in SMEM.
//    Side duties (overlapped): 6 f_k mask samples per block; block 0 zeroes
//    the stats accumulators + done counter (all consumed only by k_stats).
// ---------------------------------------------------------------------------
__global__ void k_dist(const float* __restrict__ sel_s,
                       const float* __restrict__ ker_s,
                       const float* __restrict__ sel_l,
                       const float* __restrict__ ker_l,
                       const float* __restrict__ fk) {
    __shared__ float sa[CC];
    int lb = blockIdx.y;   // l*B + b
    int l  = lb / BB;
    int scale = (blockIdx.x >= NBS) ? 1 : 0;
    int bx = scale ? (blockIdx.x - NBS) : blockIdx.x;
    int N = scale ? NL : NS;
    const float* sel = scale ? sel_l : sel_s;
    const float* ker = scale ? ker_l : ker_s;

    // --- side duty A: f_k mask sampling (6 samples per block, overlapped) ---
    {
        int bid = blockIdx.y * GDX + blockIdx.x;
        int s = bid * 6 + threadIdx.x;
        if (threadIdx.x < 6 && s < NSAMP) {
            if (s < BB*VS) {
                int b = s / VS, p = s % VS;
                int i = p / GS, j = p % GS;
                g_valid_s[s] = fk[(size_t)b*HH*WW + (size_t)i*8*WW + j*8] > 0.f;
            } else {
                int u = s - BB*VS;
                int b = u / VL, p = u % VL;
                int i = p / GL, j = p % GL;
                g_valid_l[u] = fk[(size_t)b*HH*WW + (size_t)i*28*WW + j*28] > 0.f;
            }
        }
        // --- side duty B: zero stats accumulators (block 0 only) ---
        if (bid == 0) {
            if (threadIdx.x >= 8 && threadIdx.x < 8 + 2*LB) {
                int t = threadIdx.x - 8;
                g_sp[t] = 0.f; g_sn[t] = 0.f; g_cp[t] = 0; g_cn[t] = 0;
            }
            if (threadIdx.x == 7) g_done = 0u;
        }
    }

    const float* a = ker + (size_t)lb * CC;   // kernel (L,B,C,1) -> contiguous C
    for (int i = threadIdx.x; i < CC; i += blockDim.x) sa[i] = a[i];
    __syncthreads();

    int warp = threadIdx.x >> 5;
    int lane = threadIdx.x & 31;
    int n = bx * 8 + warp;

    const float4* row = (const float4*)(sel + ((size_t)lb * N + n) * CC);
    const float4* av  = (const float4*)sa;

    float s2 = 0.f, sab = 0.f;
#pragma unroll
    for (int k = 0; k < CC/128; k++) {   // 6 iterations, 192 float4 per row
        float4 v  = row[k*32 + lane];
        float4 aa = av [k*32 + lane];
        float d0 = aa.x - v.x, d1 = aa.y - v.y;
        float d2 = aa.z - v.z, d3 = aa.w - v.w;
        s2  = fmaf(d0, d0, s2); s2 = fmaf(d1, d1, s2);
        s2  = fmaf(d2, d2, s2); s2 = fmaf(d3, d3, s2);
        sab += fabsf(v.x) + fabsf(v.y) + fabsf(v.z) + fabsf(v.w);
    }
#pragma unroll
    for (int o = 16; o; o >>= 1) {
        s2  += __shfl_xor_sync(0xFFFFFFFFu, s2,  o);
        sab += __shfl_xor_sync(0xFFFFFFFFu, sab, o);
    }
    if (lane == 0) {
        int b = lb % BB;
        size_t off = (size_t)lb * N + n;
        unsigned char nz = (sab != 0.f) ? 1 : 0;
        if (scale == 0) {
            g_dist_s[off] = sqrtf(s2);
            g_nz_s[((size_t)l*NS + n)*8 + b] = nz;
        } else {
            g_dist_l[off] = sqrtf(s2);
            g_nz_l[((size_t)l*NL + n)*8 + b] = nz;
        }
    }
}

// ---------------------------------------------------------------------------
// 2) Masked accumulation + fused last-block finalization.
//    grid = (STATS_BX, 64): blockIdx.y = gb (scale*LB + lb).
//    colv via one 8-byte nz word; membership via precomputed valid bytes.
// ---------------------------------------------------------------------------
__global__ void k_stats(const int* __restrict__ idx_s,
                        const int* __restrict__ idx_l,
                        float* __restrict__ out) {
    int gb = blockIdx.y;
    int scale = gb / LB;      // 0 = s, 1 = l
    int lb = gb % LB;
    int l = lb / BB, b = lb % BB;
    int N = scale ? NL : NS;
    int V = scale ? VL : VS;
    const float* dist = scale ? g_dist_l : g_dist_s;
    const unsigned char* nz = scale ? g_nz_l : g_nz_s;
    const unsigned char* valid = scale ? g_valid_l : g_valid_s;
    const int* idx = scale ? idx_l : idx_s;

    int n = blockIdx.x * blockDim.x + threadIdx.x;
    float sp = 0.f, sn = 0.f;
    int   cp = 0,   cn = 0;
    if (n < N) {
        unsigned long long w =
            *(const unsigned long long*)(nz + ((size_t)l*N + n)*8);
        if (w != 0ull) {
            int id = idx[((size_t)l*BB + b)*N + n];
            float d = dist[(size_t)lb*N + n];
            bool mem = valid[b*V + id] != 0;
            if (mem) { sp = d; cp = 1; } else { sn = d; cn = 1; }
        }
    }

#pragma unroll
    for (int o = 16; o; o >>= 1) {
        sp += __shfl_xor_sync(0xFFFFFFFFu, sp, o);
        sn += __shfl_xor_sync(0xFFFFFFFFu, sn, o);
        cp += __shfl_xor_sync(0xFFFFFFFFu, cp, o);
        cn += __shfl_xor_sync(0xFFFFFFFFu, cn, o);
    }
    if ((threadIdx.x & 31) == 0) {
        if (sp != 0.f) atomicAdd(&g_sp[gb], sp);
        if (sn != 0.f) atomicAdd(&g_sn[gb], sn);
        if (cp)        atomicAdd(&g_cp[gb], cp);
        if (cn)        atomicAdd(&g_cn[gb], cn);
    }

    // ---- last-block finalization ----
    __shared__ bool is_last;
    __syncthreads();              // all block atomics issued
    if (threadIdx.x == 0) {
        __threadfence();
        unsigned prev = atomicAdd(&g_done, 1u);
        is_last = (prev == STATS_BLOCKS - 1);
    }
    __syncthreads();
    if (!is_last) return;

    __shared__ float s_loss[2*LB];
    __shared__ int   s_act [2*LB];
    int t = threadIdx.x;
    if (t < 2*LB) {
        int tcp = g_cp[t], tcn = g_cn[t];
        float ap = g_sp[t] / (float)(tcp > 1 ? tcp : 1);
        float an = g_sn[t] / (float)(tcn > 1 ? tcn : 1);
        float x = ap - an;
        float loss = (x > 0.f) ? (x + log1pf(expf(-x))) : log1pf(expf(x));
        s_loss[t] = loss;
        s_act[t]  = (tcp > 0 && tcn > 0) ? 1 : 0;
    }
    __syncthreads();
    if (t < 64) {
        float v = 0.f; int c = 0;
        if (t < LB) {                       // small scale: act_s
            if (s_act[t]) { v = s_loss[t]; c = 1; }
        } else {                            // large scale: act_l & act_s
            if (s_act[t] && s_act[t - LB]) { v = s_loss[t]; c = 1; }
        }
#pragma unroll
        for (int o = 16; o; o >>= 1) {
            v += __shfl_xor_sync(0xFFFFFFFFu, v, o);
            c += __shfl_xor_sync(0xFFFFFFFFu, c, o);
        }
        __shared__ float sv[2]; __shared__ int sc[2];
        int warp = t >> 5;
        if ((t & 31) == 0) { sv[warp] = v; sc[warp] = c; }
        __syncthreads();
        if (t == 0) {
            float total = sv[0] + sv[1];
            int times = sc[0] + sc[1];
            out[0] = (times > 0) ? total / (float)times : 0.f;
        }
    }
}

// ---------------------------------------------------------------------------
extern "C" void kernel_launch(void* const* d_in, const int* in_sizes, int n_in,
                              void* d_out, int out_size) {
    const float* sel_s = (const float*)d_in[0];
    const int*   idx_s = (const int*)  d_in[1];
    const float* sel_l = (const float*)d_in[2];
    const int*   idx_l = (const int*)  d_in[3];
    const float* ker_s = (const float*)d_in[4];
    const float* ker_l = (const float*)d_in[5];
    const float* fk    = (const float*)d_in[6];

    dim3 gd(GDX, LB);   // (166, 32)
    k_dist<<<gd, 256>>>(sel_s, ker_s, sel_l, ker_l, fk);

    dim3 gst(STATS_BX, 2*LB);   // (5, 64) = 320 blocks
    k_stats<<<gst, 256>>>(idx_s, idx_l, (float*)d_out);
}

// round 7
// speedup vs baseline: 1.1164x; 1.0300x over previous
#include <cuda_runtime.h>
#include <math.h>

// Problem constants (fixed shapes from setup_inputs)
#define LL 4
#define BB 8
#define NS 1200
#define NL 128
#define CC 768
#define HH 448
#define WW 448
#define GS 56            // H/8   (grid cols, small)
#define GL 16            // H/28  (grid cols, large)
#define VS (GS*GS)       // 3136
#define VL (GL*GL)       // 256
#define LB (LL*BB)       // 32
#define NBS 150          // blocks per lb, small scale (1200/8)
#define NBL 16           // blocks per lb, large scale (128/8)
#define GDX (NBS+NBL)    // 166
#define NSAMP (BB*VS + BB*VL)   // 27136 mask samples
#define STATS_BLOCKS (2*LB)     // 64

// Scratch (no allocations -> __device__ globals). Device-code refs only.
__device__ float g_dist_s[LB*NS];
__device__ float g_dist_l[LB*NL];
__device__ unsigned char g_nz_s[LL*NS*8];   // [l][n][b] nonzero flags
__device__ unsigned char g_nz_l[LL*NL*8];
__device__ unsigned char g_valid_s[BB*VS];
__device__ unsigned char g_valid_l[BB*VL];
__device__ float g_sp[2*LB];
__device__ float g_sn[2*LB];
__device__ int   g_cp[2*LB];
__device__ int   g_cn[2*LB];
__device__ unsigned g_done;

// ---------------------------------------------------------------------------
// 1) Main HBM-bound pass (both scales, one launch).
//    Per row (l,b,n): dist = sqrt(sum_c (anchor-sel)^2); nz byte = (sum|sel|!=0).
//    One warp per row, float4 loads, anchor staged in SMEM.
//    Side duties (overlapped): 6 f_k mask samples per block; block 0 resets
//    the done counter (consumed only by k_stats, after kernel boundary).
// ---------------------------------------------------------------------------
__global__ void k_dist(const float* __restrict__ sel_s,
                       const float* __restrict__ ker_s,
                       const float* __restrict__ sel_l,
                       const float* __restrict__ ker_l,
                       const float* __restrict__ fk) {
    __shared__ float sa[CC];
    int lb = blockIdx.y;   // l*B + b
    int l  = lb / BB;
    int scale = (blockIdx.x >= NBS) ? 1 : 0;
    int bx = scale ? (blockIdx.x - NBS) : blockIdx.x;
    int N = scale ? NL : NS;
    const float* sel = scale ? sel_l : sel_s;
    const float* ker = scale ? ker_l : ker_s;

    // --- side duty: f_k mask sampling (6 samples per block, overlapped) ---
    {
        int bid = blockIdx.y * GDX + blockIdx.x;
        int s = bid * 6 + threadIdx.x;
        if (threadIdx.x < 6 && s < NSAMP) {
            if (s < BB*VS) {
                int b = s / VS, p = s % VS;
                int i = p / GS, j = p % GS;
                g_valid_s[s] = fk[(size_t)b*HH*WW + (size_t)i*8*WW + j*8] > 0.f;
            } else {
                int u = s - BB*VS;
                int b = u / VL, p = u % VL;
                int i = p / GL, j = p % GL;
                g_valid_l[u] = fk[(size_t)b*HH*WW + (size_t)i*28*WW + j*28] > 0.f;
            }
        }
        if (bid == 0 && threadIdx.x == 7) g_done = 0u;
    }

    const float* a = ker + (size_t)lb * CC;   // kernel (L,B,C,1) -> contiguous C
    for (int i = threadIdx.x; i < CC; i += blockDim.x) sa[i] = a[i];
    __syncthreads();

    int warp = threadIdx.x >> 5;
    int lane = threadIdx.x & 31;
    int n = bx * 8 + warp;

    const float4* row = (const float4*)(sel + ((size_t)lb * N + n) * CC);
    const float4* av  = (const float4*)sa;

    float s2 = 0.f, sab = 0.f;
#pragma unroll
    for (int k = 0; k < CC/128; k++) {   // 6 iterations, 192 float4 per row
        float4 v  = row[k*32 + lane];
        float4 aa = av [k*32 + lane];
        float d0 = aa.x - v.x, d1 = aa.y - v.y;
        float d2 = aa.z - v.z, d3 = aa.w - v.w;
        s2  = fmaf(d0, d0, s2); s2 = fmaf(d1, d1, s2);
        s2  = fmaf(d2, d2, s2); s2 = fmaf(d3, d3, s2);
        sab += fabsf(v.x) + fabsf(v.y) + fabsf(v.z) + fabsf(v.w);
    }
#pragma unroll
    for (int o = 16; o; o >>= 1) {
        s2  += __shfl_xor_sync(0xFFFFFFFFu, s2,  o);
        sab += __shfl_xor_sync(0xFFFFFFFFu, sab, o);
    }
    if (lane == 0) {
        int b = lb % BB;
        size_t off = (size_t)lb * N + n;
        unsigned char nz = (sab != 0.f) ? 1 : 0;
        if (scale == 0) {
            g_dist_s[off] = sqrtf(s2);
            g_nz_s[((size_t)l*NS + n)*8 + b] = nz;
        } else {
            g_dist_l[off] = sqrtf(s2);
            g_nz_l[((size_t)l*NL + n)*8 + b] = nz;
        }
    }
}

// ---------------------------------------------------------------------------
// 2) Masked accumulation, one block per gb (64 blocks), MLP-5 unrolled loads,
//    deterministic block reduce, direct (non-atomic) result write,
//    fused last-block finalization.
// ---------------------------------------------------------------------------
__global__ void k_stats(const int* __restrict__ idx_s,
                        const int* __restrict__ idx_l,
                        float* __restrict__ out) {
    int gb = blockIdx.x;
    int scale = gb / LB;      // 0 = s, 1 = l
    int lb = gb % LB;
    int l = lb / BB, b = lb % BB;
    int N = scale ? NL : NS;
    int V = scale ? VL : VS;
    const float* dist = scale ? g_dist_l : g_dist_s;
    const unsigned char* nz = scale ? g_nz_l : g_nz_s;
    const unsigned char* valid = scale ? g_valid_l : g_valid_s;
    const int* idx = scale ? idx_l : idx_s;

    // Gather phase: 5 independent element loads per thread (MLP).
    unsigned long long w[5];
    int   id[5];
    float d [5];
#pragma unroll
    for (int k = 0; k < 5; k++) {
        int n = k * 256 + threadIdx.x;
        bool ok = n < N;              // large scale: only k=0 survives
        w[k]  = ok ? *(const unsigned long long*)(nz + ((size_t)l*N + n)*8) : 0ull;
        id[k] = ok ? idx[((size_t)l*BB + b)*N + n] : 0;
        d[k]  = ok ? dist[(size_t)lb*N + n] : 0.f;
    }

    float sp = 0.f, sn = 0.f;
    int   cp = 0,   cn = 0;
#pragma unroll
    for (int k = 0; k < 5; k++) {
        if (w[k] != 0ull) {
            bool mem = valid[b*V + id[k]] != 0;   // 5 independent gathers
            if (mem) { sp += d[k]; cp++; } else { sn += d[k]; cn++; }
        }
    }

    // Deterministic block reduce: warp shuffle, then smem, then warp 0.
#pragma unroll
    for (int o = 16; o; o >>= 1) {
        sp += __shfl_xor_sync(0xFFFFFFFFu, sp, o);
        sn += __shfl_xor_sync(0xFFFFFFFFu, sn, o);
        cp += __shfl_xor_sync(0xFFFFFFFFu, cp, o);
        cn += __shfl_xor_sync(0xFFFFFFFFu, cn, o);
    }
    __shared__ float rsp[8], rsn[8];
    __shared__ int   rcp[8], rcn[8];
    int warp = threadIdx.x >> 5;
    if ((threadIdx.x & 31) == 0) { rsp[warp]=sp; rsn[warp]=sn; rcp[warp]=cp; rcn[warp]=cn; }
    __syncthreads();
    if (threadIdx.x == 0) {
        float tsp = 0.f, tsn = 0.f; int tcp = 0, tcn = 0;
#pragma unroll
        for (int v2 = 0; v2 < 8; v2++) {
            tsp += rsp[v2]; tsn += rsn[v2]; tcp += rcp[v2]; tcn += rcn[v2];
        }
        g_sp[gb] = tsp; g_sn[gb] = tsn; g_cp[gb] = tcp; g_cn[gb] = tcn;
    }

    // ---- last-block finalization ----
    __shared__ bool is_last;
    __syncthreads();
    if (threadIdx.x == 0) {
        __threadfence();
        unsigned prev = atomicAdd(&g_done, 1u);
        is_last = (prev == STATS_BLOCKS - 1);
    }
    __syncthreads();
    if (!is_last) return;

    __shared__ float s_loss[2*LB];
    __shared__ int   s_act [2*LB];
    int t = threadIdx.x;
    if (t < 2*LB) {
        int tcp = g_cp[t], tcn = g_cn[t];
        float ap = g_sp[t] / (float)(tcp > 1 ? tcp : 1);
        float an = g_sn[t] / (float)(tcn > 1 ? tcn : 1);
        float x = ap - an;
        float loss = (x > 0.f) ? (x + log1pf(expf(-x))) : log1pf(expf(x));
        s_loss[t] = loss;
        s_act[t]  = (tcp > 0 && tcn > 0) ? 1 : 0;
    }
    __syncthreads();
    if (t < 64) {
        float v = 0.f; int c = 0;
        if (t < LB) {                       // small scale: act_s
            if (s_act[t]) { v = s_loss[t]; c = 1; }
        } else {                            // large scale: act_l & act_s
            if (s_act[t] && s_act[t - LB]) { v = s_loss[t]; c = 1; }
        }
#pragma unroll
        for (int o = 16; o; o >>= 1) {
            v += __shfl_xor_sync(0xFFFFFFFFu, v, o);
            c += __shfl_xor_sync(0xFFFFFFFFu, c, o);
        }
        __shared__ float sv[2]; __shared__ int sc[2];
        int w2 = t >> 5;
        if ((t & 31) == 0) { sv[w2] = v; sc[w2] = c; }
        __syncthreads();
        if (t == 0) {
            float total = sv[0] + sv[1];
            int times = sc[0] + sc[1];
            out[0] = (times > 0) ? total / (float)times : 0.f;
        }
    }
}

// ---------------------------------------------------------------------------
extern "C" void kernel_launch(void* const* d_in, const int* in_sizes, int n_in,
                              void* d_out, int out_size) {
    const float* sel_s = (const float*)d_in[0];
    const int*   idx_s = (const int*)  d_in[1];
    const float* sel_l = (const float*)d_in[2];
    const int*   idx_l = (const int*)  d_in[3];
    const float* ker_s = (const float*)d_in[4];
    const float* ker_l = (const float*)d_in[5];
    const float* fk    = (const float*)d_in[6];

    dim3 gd(GDX, LB);   // (166, 32)
    k_dist<<<gd, 256>>>(sel_s, ker_s, sel_l, ker_l, fk);

    k_stats<<<STATS_BLOCKS, 256>>>(idx_s, idx_l, (float*)d_out);
}